// round 14
// baseline (speedup 1.0000x reference)
#include <cuda_runtime.h>
#include <cuda_bf16.h>
#include <cstdint>

#define N_NODES 50000
#define N_EDGES 800000
#define CH 128          // HEADS*OUT_CH = 4*32
#define SCAN_B 256
#define NB_SCAN ((N_NODES + SCAN_B - 1) / SCAN_B)   // 196
#define N_TILES ((N_NODES + 127) / 128)              // 391
#define NB_MMA (N_TILES * 4)                         // 1564: tile x mat x nhalf

// ---------------- scratch (static device memory; zero-init at load) ----------
__device__ __align__(16) float g_xl[N_NODES * CH];
__device__ __align__(16) float g_xr[N_NODES * CH];
__device__ int g_cnt[N_NODES];        // zero-init; consumed+re-zeroed in-kernel
__device__ int g_off[N_NODES + 1];
__device__ int g_esrc[N_EDGES];
__device__ int g_bsum[NB_SCAN];
__device__ int g_sync0, g_sync1, g_sync2, g_sync3;   // self-resetting counters

// ---------------- helpers -----------------------------------------------------
__device__ __forceinline__ uint32_t smem_u32(const void* p) {
    uint32_t a;
    asm("{ .reg .u64 t; cvta.to.shared.u64 t, %1; cvt.u32.u64 %0, t; }"
        : "=r"(a) : "l"(p));
    return a;
}
// bf16 split of a float pair -> packed hi word + lo word
__device__ __forceinline__ void split2(float a, float b,
                                       uint32_t& hi, uint32_t& lo) {
    __nv_bfloat162 h = __floats2bfloat162_rn(a, b);
    float ra = a - __bfloat162float(h.x);
    float rb = b - __bfloat162float(h.y);
    __nv_bfloat162 l = __floats2bfloat162_rn(ra, rb);
    hi = *(uint32_t*)&h;
    lo = *(uint32_t*)&l;
}
__device__ __forceinline__ void ldsm_x4(uint32_t* r, uint32_t addr) {
    asm volatile("ldmatrix.sync.aligned.m8n8.x4.shared.b16 {%0,%1,%2,%3}, [%4];"
                 : "=r"(r[0]), "=r"(r[1]), "=r"(r[2]), "=r"(r[3]) : "r"(addr));
}
__device__ __forceinline__ void ldsm_x2(uint32_t* r, uint32_t addr) {
    asm volatile("ldmatrix.sync.aligned.m8n8.x2.shared.b16 {%0,%1}, [%2];"
                 : "=r"(r[0]), "=r"(r[1]) : "r"(addr));
}
__device__ __forceinline__ void mma16816(float* d, const uint32_t* a,
                                         const uint32_t* b) {
    asm volatile(
        "mma.sync.aligned.m16n8k16.row.col.f32.bf16.bf16.f32 "
        "{%0,%1,%2,%3}, {%4,%5,%6,%7}, {%8,%9}, {%0,%1,%2,%3};"
        : "+f"(d[0]), "+f"(d[1]), "+f"(d[2]), "+f"(d[3])
        : "r"(a[0]), "r"(a[1]), "r"(a[2]), "r"(a[3]), "r"(b[0]), "r"(b[1]));
}

// ---------------- K1: fused CSR build (196 blocks) + bf16x3 HMMA GEMM --------
#define PITCH 40
#define A_HL_OFF (128 * PITCH * 2)
#define W_HL_OFF (64 * PITCH * 2)

__global__ __launch_bounds__(256)
void csr_gemm_kernel(const float* __restrict__ X,
                     const int* __restrict__ ei,
                     const float* __restrict__ Wl, const float* __restrict__ bl,
                     const float* __restrict__ Wr, const float* __restrict__ br) {
    const int tid  = threadIdx.x;
    const int lane = tid & 31;

    if (blockIdx.x < NB_SCAN) {            // ================= CSR path =======
        __shared__ int ws[8];
        __shared__ int s_base;
        const int b   = blockIdx.x;
        const int wid = tid >> 5;

        for (int e = b * SCAN_B + tid; e < N_EDGES; e += NB_SCAN * SCAN_B)
            atomicAdd(&g_cnt[ei[N_EDGES + e]], 1);
        __threadfence();
        __syncthreads();
        if (tid == 0) {
            atomicAdd(&g_sync0, 1);
            while (*(volatile int*)&g_sync0 < NB_SCAN) {}
            __threadfence();
        }
        __syncthreads();

        int idx = b * SCAN_B + tid;
        int v = 0;
        if (idx < N_NODES) { v = g_cnt[idx]; g_cnt[idx] = 0; }
        int s = v;
#pragma unroll
        for (int o = 1; o < 32; o <<= 1) {
            int u = __shfl_up_sync(0xffffffffu, s, o);
            if (lane >= o) s += u;
        }
        if (lane == 31) ws[wid] = s;
        __syncthreads();
        if (wid == 0) {
            int t = (lane < 8) ? ws[lane] : 0;
#pragma unroll
            for (int o = 1; o < 8; o <<= 1) {
                int u = __shfl_up_sync(0xffffffffu, t, o, 8);
                if ((lane & 7) >= o) t += u;
            }
            if (lane < 8) ws[lane] = t;
        }
        __syncthreads();
        int blocksum   = ws[7];
        int local_excl = (wid ? ws[wid - 1] : 0) + s - v;
        __syncthreads();

        if (tid == 0) {
            g_bsum[b] = blocksum;
            __threadfence();
            atomicAdd(&g_sync1, 1);
            while (*(volatile int*)&g_sync1 < NB_SCAN) {}
            __threadfence();
        }
        __syncthreads();

        int pv = (tid < b) ? g_bsum[tid] : 0;
#pragma unroll
        for (int o = 16; o > 0; o >>= 1)
            pv += __shfl_xor_sync(0xffffffffu, pv, o);
        if (lane == 0) ws[wid] = pv;
        __syncthreads();
        if (tid == 0) {
            int tot = 0;
#pragma unroll
            for (int i = 0; i < 8; i++) tot += ws[i];
            s_base = tot;
        }
        __syncthreads();
        int base = s_base;

        if (idx < N_NODES) g_off[idx] = base + local_excl;
        if (b == NB_SCAN - 1 && tid == 0) g_off[N_NODES] = base + blocksum;

        if (tid == 0) {
            __threadfence();
            atomicAdd(&g_sync2, 1);
            while (*(volatile int*)&g_sync2 < NB_SCAN) {}
            __threadfence();
            int t3 = atomicAdd(&g_sync3, 1);
            if (t3 == NB_SCAN - 1) {
                g_sync0 = 0; g_sync1 = 0; g_sync2 = 0; g_sync3 = 0;
            }
        }
        __syncthreads();

        for (int e = b * SCAN_B + tid; e < N_EDGES; e += NB_SCAN * SCAN_B) {
            int sp = ei[e];
            int tg = ei[N_EDGES + e];
            int pos = atomicAdd(&g_off[tg], 1);
            g_esrc[pos] = sp;
        }
        return;
    }

    // ================= GEMM path =============================================
    __shared__ __align__(16) uint16_t As[2][128 * PITCH];
    __shared__ __align__(16) uint16_t Ws[2][64 * PITCH];

    const int gb   = blockIdx.x - NB_SCAN;
    const int tile = gb >> 2;
    const int mat  = (gb >> 1) & 1;
    const int nh   = gb & 1;
    const int nb   = tile * 128;
    const int o0   = nh * 64;
    const float* W    = mat ? Wr : Wl;
    const float* bias = mat ? br : bl;
    float* dst        = mat ? g_xr : g_xl;

    const int warp = tid >> 5;
    const int m_warp = (warp & 3) * 32;
    const int n_warp = (warp >> 2) * 32;

    const uint32_t as_base = smem_u32(As);
    const uint32_t ws_base = smem_u32(Ws);

    float acc[2][4][4];
#pragma unroll
    for (int mt = 0; mt < 2; mt++)
#pragma unroll
        for (int nt = 0; nt < 4; nt++)
#pragma unroll
            for (int q = 0; q < 4; q++) acc[mt][nt][q] = 0.f;

    const int arow = lane & 15;
    const int acol8 = (lane >> 4) << 3;
    const int brow = lane & 7;
    const int bcol8 = ((lane >> 3) & 1) << 3;

    for (int kt = 0; kt < CH; kt += 32) {
#pragma unroll
        for (int t = 0; t < 4; t++) {
            int idx = tid + t * 256;
            int row = idx >> 3;
            int kq  = (idx & 7) << 2;
            int gn  = nb + row;
            float4 v = make_float4(0.f, 0.f, 0.f, 0.f);
            if (gn < N_NODES) v = *(const float4*)(X + gn * CH + kt + kq);
            uint32_t h0, l0, h1, l1;
            split2(v.x, v.y, h0, l0);
            split2(v.z, v.w, h1, l1);
            int sw = (row * PITCH + kq) >> 1;
            ((uint32_t*)As[0])[sw]     = h0;
            ((uint32_t*)As[0])[sw + 1] = h1;
            ((uint32_t*)As[1])[sw]     = l0;
            ((uint32_t*)As[1])[sw + 1] = l1;
        }
#pragma unroll
        for (int t = 0; t < 2; t++) {
            int idx = tid + t * 256;
            int row = idx >> 3;
            int kq  = (idx & 7) << 2;
            float4 v = *(const float4*)(W + (o0 + row) * CH + kt + kq);
            uint32_t h0, l0, h1, l1;
            split2(v.x, v.y, h0, l0);
            split2(v.z, v.w, h1, l1);
            int sw = (row * PITCH + kq) >> 1;
            ((uint32_t*)Ws[0])[sw]     = h0;
            ((uint32_t*)Ws[0])[sw + 1] = h1;
            ((uint32_t*)Ws[1])[sw]     = l0;
            ((uint32_t*)Ws[1])[sw + 1] = l1;
        }
        __syncthreads();

#pragma unroll
        for (int ks = 0; ks < 32; ks += 16) {
            uint32_t ah[2][4], alo[2][4];
#pragma unroll
            for (int mt = 0; mt < 2; mt++) {
                uint32_t adr = as_base +
                    ((m_warp + mt * 16 + arow) * PITCH + ks + acol8) * 2;
                ldsm_x4(ah[mt], adr);
                ldsm_x4(alo[mt], adr + A_HL_OFF);
            }
            uint32_t bh[4][2], blo2[4][2];
#pragma unroll
            for (int nt = 0; nt < 4; nt++) {
                uint32_t adr = ws_base +
                    ((n_warp + nt * 8 + brow) * PITCH + ks + bcol8) * 2;
                ldsm_x2(bh[nt], adr);
                ldsm_x2(blo2[nt], adr + W_HL_OFF);
            }
#pragma unroll
            for (int mt = 0; mt < 2; mt++)
#pragma unroll
                for (int nt = 0; nt < 4; nt++) {
                    mma16816(acc[mt][nt], ah[mt], bh[nt]);
                    mma16816(acc[mt][nt], ah[mt], blo2[nt]);
                    mma16816(acc[mt][nt], alo[mt], bh[nt]);
                }
        }
        __syncthreads();
    }

    const int r0 = lane >> 2;
    const int c0 = (lane & 3) << 1;
#pragma unroll
    for (int mt = 0; mt < 2; mt++) {
        int m0 = nb + m_warp + mt * 16 + r0;
#pragma unroll
        for (int nt = 0; nt < 4; nt++) {
            int o = o0 + n_warp + nt * 8 + c0;
            float b0 = __ldg(&bias[o]);
            float b1 = __ldg(&bias[o + 1]);
            if (m0 < N_NODES) {
                float2 r = make_float2(acc[mt][nt][0] + b0, acc[mt][nt][1] + b1);
                *(float2*)(dst + m0 * CH + o) = r;
            }
            if (m0 + 8 < N_NODES) {
                float2 r = make_float2(acc[mt][nt][2] + b0, acc[mt][nt][3] + b1);
                *(float2*)(dst + (m0 + 8) * CH + o) = r;
            }
        }
    }
}

// ---------------- K2: warp-per-node online-softmax, 8-edge gather-twice ------
// leaky(s) = 0.6s + 0.4|s| (NEG_SLOPE=0.2), folded into scaled att vectors.
// 8-edge batch with TRANSIENT gathers: logits computed from a 4-wide reused
// buffer; accumulation re-gathers the same rows (L1-hot). No remainder loop —
// partial batches handled by clamping src and forcing logits to -1e30.
__global__ __launch_bounds__(256, 4)
void agg_kernel(const float* __restrict__ att,
                const float* __restrict__ bias,
                float* __restrict__ out) {
    int w    = (blockIdx.x * blockDim.x + threadIdx.x) >> 5;
    int lane = threadIdx.x & 31;
    if (w >= N_NODES) return;
    const int i  = w;
    const int c0 = lane << 2;

    const float4 xlv = *(const float4*)(g_xl + i * CH + c0);
    const float4 av  = *(const float4*)(att + c0);
    const float4 xrs = *(const float4*)(g_xr + i * CH + c0);
    const float4 a6 = make_float4(0.6f * av.x, 0.6f * av.y,
                                  0.6f * av.z, 0.6f * av.w);
    const float4 a4 = make_float4(0.4f * av.x, 0.4f * av.y,
                                  0.4f * av.z, 0.4f * av.w);

    // self-loop logit
    float s0 = xlv.x + xrs.x, s1 = xlv.y + xrs.y;
    float s2 = xlv.z + xrs.z, s3 = xlv.w + xrs.w;
    float p = a6.x * s0 + a4.x * fabsf(s0);
    p += a6.y * s1 + a4.y * fabsf(s1);
    p += a6.z * s2 + a4.z * fabsf(s2);
    p += a6.w * s3 + a4.w * fabsf(s3);
#pragma unroll
    for (int o = 1; o < 8; o <<= 1) p += __shfl_xor_sync(0xffffffffu, p, o);

    float m = p;
    float d = 1.0f;
    float4 acc = xrs;

    const int beg = i ? __ldg(&g_off[i - 1]) : 0;
    const int end = __ldg(&g_off[i]);

    for (int e = beg; e < end; e += 8) {
        const int cnt = end - e;            // >= 1; valid edges = min(cnt, 8)
        int src[8];
#pragma unroll
        for (int j = 0; j < 8; j++)
            src[j] = __ldg(&g_esrc[(j < cnt) ? e + j : e]);

        // ---- logit pass (transient 4-wide gather buffer) ----
        float pj[8];
#pragma unroll
        for (int c2 = 0; c2 < 2; c2++) {
            float4 xv[4];
#pragma unroll
            for (int j = 0; j < 4; j++)
                xv[j] = *(const float4*)(g_xr + src[c2 * 4 + j] * CH + c0);
#pragma unroll
            for (int j = 0; j < 4; j++) {
                float t0 = xlv.x + xv[j].x;
                float t1 = xlv.y + xv[j].y;
                float t2 = xlv.z + xv[j].z;
                float t3 = xlv.w + xv[j].w;
                float q = a6.x * t0 + a4.x * fabsf(t0);
                q += a6.y * t1 + a4.y * fabsf(t1);
                q += a6.z * t2 + a4.z * fabsf(t2);
                q += a6.w * t3 + a4.w * fabsf(t3);
                pj[c2 * 4 + j] = q;
            }
        }

        // ---- butterfly transpose-reduce: lane (g*8+j) -> edge j, head g ----
        {
            bool b0 = lane & 1;
#pragma unroll
            for (int k = 0; k < 4; k++) {
                float snd = b0 ? pj[2 * k] : pj[2 * k + 1];
                float kp  = b0 ? pj[2 * k + 1] : pj[2 * k];
                pj[k] = kp + __shfl_xor_sync(0xffffffffu, snd, 1);
            }
            bool b1 = lane & 2;
#pragma unroll
            for (int k = 0; k < 2; k++) {
                float snd = b1 ? pj[2 * k] : pj[2 * k + 1];
                float kp  = b1 ? pj[2 * k + 1] : pj[2 * k];
                pj[k] = kp + __shfl_xor_sync(0xffffffffu, snd, 2);
            }
            bool b2 = lane & 4;
            {
                float snd = b2 ? pj[0] : pj[1];
                float kp  = b2 ? pj[1] : pj[0];
                pj[0] = kp + __shfl_xor_sync(0xffffffffu, snd, 4);
            }
        }
        float q = ((lane & 7) < cnt) ? pj[0] : -1e30f;   // mask invalid edges
        float qm = q;
        qm = fmaxf(qm, __shfl_xor_sync(0xffffffffu, qm, 1));
        qm = fmaxf(qm, __shfl_xor_sync(0xffffffffu, qm, 2));
        qm = fmaxf(qm, __shfl_xor_sync(0xffffffffu, qm, 4));
        float nm = fmaxf(m, qm);
        float wq = __expf(q - nm);           // 0 for invalid edges
        float wm = __expf(m - nm);
        m = nm;

        float wv[8];
        int gbase = lane & 24;
#pragma unroll
        for (int j = 0; j < 8; j++)
            wv[j] = __shfl_sync(0xffffffffu, wq, gbase + j);
        float dsum = ((wv[0] + wv[1]) + (wv[2] + wv[3])) +
                     ((wv[4] + wv[5]) + (wv[6] + wv[7]));
        d = d * wm + dsum;
        acc.x *= wm; acc.y *= wm; acc.z *= wm; acc.w *= wm;

        // ---- accumulate pass: re-gather (L1-hot), weight-0 for invalid ----
#pragma unroll
        for (int j = 0; j < 8; j++) {
            float4 xv = *(const float4*)(g_xr + src[j] * CH + c0);
            acc.x += wv[j] * xv.x;
            acc.y += wv[j] * xv.y;
            acc.z += wv[j] * xv.z;
            acc.w += wv[j] * xv.w;
        }
    }

    float inv = 1.0f / d;
    const float4 bv = *(const float4*)(bias + c0);
    float4 r = make_float4(acc.x * inv + bv.x, acc.y * inv + bv.y,
                           acc.z * inv + bv.z, acc.w * inv + bv.w);
    *(float4*)(out + i * CH + c0) = r;
}

// ---------------- launch ------------------------------------------------------
extern "C" void kernel_launch(void* const* d_in, const int* in_sizes, int n_in,
                              void* d_out, int out_size) {
    const float* x    = (const float*)d_in[0];
    const int*   ei   = (const int*)d_in[1];     // int32 (JAX x64 disabled)
    const float* Wl   = (const float*)d_in[2];
    const float* bl   = (const float*)d_in[3];
    const float* Wr   = (const float*)d_in[4];
    const float* br   = (const float*)d_in[5];
    const float* att  = (const float*)d_in[6];
    const float* bias = (const float*)d_in[7];
    float*       out  = (float*)d_out;

    csr_gemm_kernel<<<NB_SCAN + NB_MMA, 256>>>(x, ei, Wl, bl, Wr, br);
    agg_kernel<<<(N_NODES * 32 + 255) / 256, 256>>>(att, bias, out);
}

// round 15
// speedup vs baseline: 1.0676x; 1.0676x over previous
#include <cuda_runtime.h>
#include <cuda_bf16.h>
#include <cstdint>

#define N_NODES 50000
#define N_EDGES 800000
#define CH 128          // HEADS*OUT_CH = 4*32
#define SCAN_B 256
#define NB_SCAN ((N_NODES + SCAN_B - 1) / SCAN_B)   // 196
#define N_TILES ((N_NODES + 127) / 128)              // 391
#define NB_MMA (N_TILES * 4)                         // 1564: tile x mat x nhalf

// ---------------- scratch (static device memory; zero-init at load) ----------
__device__ __align__(16) float g_xl[N_NODES * CH];
__device__ __align__(16) float g_xr[N_NODES * CH];
__device__ int g_cnt[N_NODES];        // zero-init; consumed+re-zeroed in-kernel
__device__ int g_off[N_NODES + 1];
__device__ int g_esrc[N_EDGES];
__device__ int g_bsum[NB_SCAN];
__device__ int g_sync0, g_sync1, g_sync2, g_sync3;   // self-resetting counters

// ---------------- helpers -----------------------------------------------------
__device__ __forceinline__ uint32_t smem_u32(const void* p) {
    uint32_t a;
    asm("{ .reg .u64 t; cvta.to.shared.u64 t, %1; cvt.u32.u64 %0, t; }"
        : "=r"(a) : "l"(p));
    return a;
}
// bf16 split of a float pair -> packed hi word + lo word
__device__ __forceinline__ void split2(float a, float b,
                                       uint32_t& hi, uint32_t& lo) {
    __nv_bfloat162 h = __floats2bfloat162_rn(a, b);
    float ra = a - __bfloat162float(h.x);
    float rb = b - __bfloat162float(h.y);
    __nv_bfloat162 l = __floats2bfloat162_rn(ra, rb);
    hi = *(uint32_t*)&h;
    lo = *(uint32_t*)&l;
}
__device__ __forceinline__ void ldsm_x4(uint32_t* r, uint32_t addr) {
    asm volatile("ldmatrix.sync.aligned.m8n8.x4.shared.b16 {%0,%1,%2,%3}, [%4];"
                 : "=r"(r[0]), "=r"(r[1]), "=r"(r[2]), "=r"(r[3]) : "r"(addr));
}
__device__ __forceinline__ void ldsm_x2(uint32_t* r, uint32_t addr) {
    asm volatile("ldmatrix.sync.aligned.m8n8.x2.shared.b16 {%0,%1}, [%2];"
                 : "=r"(r[0]), "=r"(r[1]) : "r"(addr));
}
__device__ __forceinline__ void mma16816(float* d, const uint32_t* a,
                                         const uint32_t* b) {
    asm volatile(
        "mma.sync.aligned.m16n8k16.row.col.f32.bf16.bf16.f32 "
        "{%0,%1,%2,%3}, {%4,%5,%6,%7}, {%8,%9}, {%0,%1,%2,%3};"
        : "+f"(d[0]), "+f"(d[1]), "+f"(d[2]), "+f"(d[3])
        : "r"(a[0]), "r"(a[1]), "r"(a[2]), "r"(a[3]), "r"(b[0]), "r"(b[1]));
}

// ---------------- K1: fused CSR build (196 blocks) + bf16x3 HMMA GEMM --------
#define PITCH 40
#define A_HL_OFF (128 * PITCH * 2)
#define W_HL_OFF (64 * PITCH * 2)

__global__ __launch_bounds__(256)
void csr_gemm_kernel(const float* __restrict__ X,
                     const int* __restrict__ ei,
                     const float* __restrict__ Wl, const float* __restrict__ bl,
                     const float* __restrict__ Wr, const float* __restrict__ br) {
    const int tid  = threadIdx.x;
    const int lane = tid & 31;

    if (blockIdx.x < NB_SCAN) {            // ================= CSR path =======
        __shared__ int ws[8];
        __shared__ int s_base;
        const int b   = blockIdx.x;
        const int wid = tid >> 5;

        for (int e = b * SCAN_B + tid; e < N_EDGES; e += NB_SCAN * SCAN_B)
            atomicAdd(&g_cnt[ei[N_EDGES + e]], 1);
        __threadfence();
        __syncthreads();
        if (tid == 0) {
            atomicAdd(&g_sync0, 1);
            while (*(volatile int*)&g_sync0 < NB_SCAN) {}
            __threadfence();
        }
        __syncthreads();

        int idx = b * SCAN_B + tid;
        int v = 0;
        if (idx < N_NODES) { v = g_cnt[idx]; g_cnt[idx] = 0; }
        int s = v;
#pragma unroll
        for (int o = 1; o < 32; o <<= 1) {
            int u = __shfl_up_sync(0xffffffffu, s, o);
            if (lane >= o) s += u;
        }
        if (lane == 31) ws[wid] = s;
        __syncthreads();
        if (wid == 0) {
            int t = (lane < 8) ? ws[lane] : 0;
#pragma unroll
            for (int o = 1; o < 8; o <<= 1) {
                int u = __shfl_up_sync(0xffffffffu, t, o, 8);
                if ((lane & 7) >= o) t += u;
            }
            if (lane < 8) ws[lane] = t;
        }
        __syncthreads();
        int blocksum   = ws[7];
        int local_excl = (wid ? ws[wid - 1] : 0) + s - v;
        __syncthreads();

        if (tid == 0) {
            g_bsum[b] = blocksum;
            __threadfence();
            atomicAdd(&g_sync1, 1);
            while (*(volatile int*)&g_sync1 < NB_SCAN) {}
            __threadfence();
        }
        __syncthreads();

        int pv = (tid < b) ? g_bsum[tid] : 0;
#pragma unroll
        for (int o = 16; o > 0; o >>= 1)
            pv += __shfl_xor_sync(0xffffffffu, pv, o);
        if (lane == 0) ws[wid] = pv;
        __syncthreads();
        if (tid == 0) {
            int tot = 0;
#pragma unroll
            for (int i = 0; i < 8; i++) tot += ws[i];
            s_base = tot;
        }
        __syncthreads();
        int base = s_base;

        if (idx < N_NODES) g_off[idx] = base + local_excl;
        if (b == NB_SCAN - 1 && tid == 0) g_off[N_NODES] = base + blocksum;

        if (tid == 0) {
            __threadfence();
            atomicAdd(&g_sync2, 1);
            while (*(volatile int*)&g_sync2 < NB_SCAN) {}
            __threadfence();
            int t3 = atomicAdd(&g_sync3, 1);
            if (t3 == NB_SCAN - 1) {
                g_sync0 = 0; g_sync1 = 0; g_sync2 = 0; g_sync3 = 0;
            }
        }
        __syncthreads();

        for (int e = b * SCAN_B + tid; e < N_EDGES; e += NB_SCAN * SCAN_B) {
            int sp = ei[e];
            int tg = ei[N_EDGES + e];
            int pos = atomicAdd(&g_off[tg], 1);
            g_esrc[pos] = sp;
        }
        return;
    }

    // ================= GEMM path =============================================
    __shared__ __align__(16) uint16_t As[2][128 * PITCH];
    __shared__ __align__(16) uint16_t Ws[2][64 * PITCH];

    const int gb   = blockIdx.x - NB_SCAN;
    const int tile = gb >> 2;
    const int mat  = (gb >> 1) & 1;
    const int nh   = gb & 1;
    const int nb   = tile * 128;
    const int o0   = nh * 64;
    const float* W    = mat ? Wr : Wl;
    const float* bias = mat ? br : bl;
    float* dst        = mat ? g_xr : g_xl;

    const int warp = tid >> 5;
    const int m_warp = (warp & 3) * 32;
    const int n_warp = (warp >> 2) * 32;

    const uint32_t as_base = smem_u32(As);
    const uint32_t ws_base = smem_u32(Ws);

    float acc[2][4][4];
#pragma unroll
    for (int mt = 0; mt < 2; mt++)
#pragma unroll
        for (int nt = 0; nt < 4; nt++)
#pragma unroll
            for (int q = 0; q < 4; q++) acc[mt][nt][q] = 0.f;

    const int arow = lane & 15;
    const int acol8 = (lane >> 4) << 3;
    const int brow = lane & 7;
    const int bcol8 = ((lane >> 3) & 1) << 3;

    for (int kt = 0; kt < CH; kt += 32) {
#pragma unroll
        for (int t = 0; t < 4; t++) {
            int idx = tid + t * 256;
            int row = idx >> 3;
            int kq  = (idx & 7) << 2;
            int gn  = nb + row;
            float4 v = make_float4(0.f, 0.f, 0.f, 0.f);
            if (gn < N_NODES) v = *(const float4*)(X + gn * CH + kt + kq);
            uint32_t h0, l0, h1, l1;
            split2(v.x, v.y, h0, l0);
            split2(v.z, v.w, h1, l1);
            int sw = (row * PITCH + kq) >> 1;
            ((uint32_t*)As[0])[sw]     = h0;
            ((uint32_t*)As[0])[sw + 1] = h1;
            ((uint32_t*)As[1])[sw]     = l0;
            ((uint32_t*)As[1])[sw + 1] = l1;
        }
#pragma unroll
        for (int t = 0; t < 2; t++) {
            int idx = tid + t * 256;
            int row = idx >> 3;
            int kq  = (idx & 7) << 2;
            float4 v = *(const float4*)(W + (o0 + row) * CH + kt + kq);
            uint32_t h0, l0, h1, l1;
            split2(v.x, v.y, h0, l0);
            split2(v.z, v.w, h1, l1);
            int sw = (row * PITCH + kq) >> 1;
            ((uint32_t*)Ws[0])[sw]     = h0;
            ((uint32_t*)Ws[0])[sw + 1] = h1;
            ((uint32_t*)Ws[1])[sw]     = l0;
            ((uint32_t*)Ws[1])[sw + 1] = l1;
        }
        __syncthreads();

#pragma unroll
        for (int ks = 0; ks < 32; ks += 16) {
            uint32_t ah[2][4], alo[2][4];
#pragma unroll
            for (int mt = 0; mt < 2; mt++) {
                uint32_t adr = as_base +
                    ((m_warp + mt * 16 + arow) * PITCH + ks + acol8) * 2;
                ldsm_x4(ah[mt], adr);
                ldsm_x4(alo[mt], adr + A_HL_OFF);
            }
            uint32_t bh[4][2], blo2[4][2];
#pragma unroll
            for (int nt = 0; nt < 4; nt++) {
                uint32_t adr = ws_base +
                    ((n_warp + nt * 8 + brow) * PITCH + ks + bcol8) * 2;
                ldsm_x2(bh[nt], adr);
                ldsm_x2(blo2[nt], adr + W_HL_OFF);
            }
#pragma unroll
            for (int mt = 0; mt < 2; mt++)
#pragma unroll
                for (int nt = 0; nt < 4; nt++) {
                    mma16816(acc[mt][nt], ah[mt], bh[nt]);
                    mma16816(acc[mt][nt], ah[mt], blo2[nt]);
                    mma16816(acc[mt][nt], alo[mt], bh[nt]);
                }
        }
        __syncthreads();
    }

    const int r0 = lane >> 2;
    const int c0 = (lane & 3) << 1;
#pragma unroll
    for (int mt = 0; mt < 2; mt++) {
        int m0 = nb + m_warp + mt * 16 + r0;
#pragma unroll
        for (int nt = 0; nt < 4; nt++) {
            int o = o0 + n_warp + nt * 8 + c0;
            float b0 = __ldg(&bias[o]);
            float b1 = __ldg(&bias[o + 1]);
            if (m0 < N_NODES) {
                float2 r = make_float2(acc[mt][nt][0] + b0, acc[mt][nt][1] + b1);
                *(float2*)(dst + m0 * CH + o) = r;
            }
            if (m0 + 8 < N_NODES) {
                float2 r = make_float2(acc[mt][nt][2] + b0, acc[mt][nt][3] + b1);
                *(float2*)(dst + (m0 + 8) * CH + o) = r;
            }
        }
    }
}

// ---------------- K2: warp-per-node online-softmax, 4-edge batched -----------
// leaky(s) = 0.6s + 0.4|s| (NEG_SLOPE=0.2), folded into scaled att vectors.
// Register cap: 5 CTAs/SM (<=51 regs) to lift occupancy 40% -> 50%.
__global__ __launch_bounds__(256, 5)
void agg_kernel(const float* __restrict__ att,
                const float* __restrict__ bias,
                float* __restrict__ out) {
    int w    = (blockIdx.x * blockDim.x + threadIdx.x) >> 5;
    int lane = threadIdx.x & 31;
    if (w >= N_NODES) return;
    const int i  = w;
    const int c0 = lane << 2;

    const float4 xlv = *(const float4*)(g_xl + i * CH + c0);
    const float4 av  = *(const float4*)(att + c0);
    const float4 xrs = *(const float4*)(g_xr + i * CH + c0);
    const float4 a6 = make_float4(0.6f * av.x, 0.6f * av.y,
                                  0.6f * av.z, 0.6f * av.w);
    const float4 a4 = make_float4(0.4f * av.x, 0.4f * av.y,
                                  0.4f * av.z, 0.4f * av.w);

    float s0 = xlv.x + xrs.x, s1 = xlv.y + xrs.y;
    float s2 = xlv.z + xrs.z, s3 = xlv.w + xrs.w;
    float p = a6.x * s0 + a4.x * fabsf(s0);
    p += a6.y * s1 + a4.y * fabsf(s1);
    p += a6.z * s2 + a4.z * fabsf(s2);
    p += a6.w * s3 + a4.w * fabsf(s3);
#pragma unroll
    for (int o = 1; o < 8; o <<= 1) p += __shfl_xor_sync(0xffffffffu, p, o);

    float m = p;
    float d = 1.0f;
    float4 acc = xrs;

    int e = i ? __ldg(&g_off[i - 1]) : 0;
    const int end = __ldg(&g_off[i]);

    // ---- 4-edge batches ----
    for (; e + 4 <= end; e += 4) {
        float4 xv[4];
#pragma unroll
        for (int j = 0; j < 4; j++) {
            int src = __ldg(&g_esrc[e + j]);
            xv[j] = *(const float4*)(g_xr + src * CH + c0);
        }
        float pj[4];
#pragma unroll
        for (int j = 0; j < 4; j++) {
            float t0 = xlv.x + xv[j].x;
            float t1 = xlv.y + xv[j].y;
            float t2 = xlv.z + xv[j].z;
            float t3 = xlv.w + xv[j].w;
            float q = a6.x * t0 + a4.x * fabsf(t0);
            q += a6.y * t1 + a4.y * fabsf(t1);
            q += a6.z * t2 + a4.z * fabsf(t2);
            q += a6.w * t3 + a4.w * fabsf(t3);
            pj[j] = q;
        }
        // butterfly transpose: after xor1+xor2, lane l holds edge (l&3) summed
        // over its 4-lane subgroup; xor4 add completes the 8-lane head sum.
        {
            bool b0 = lane & 1;
#pragma unroll
            for (int k = 0; k < 2; k++) {
                float snd = b0 ? pj[2 * k] : pj[2 * k + 1];
                float kp  = b0 ? pj[2 * k + 1] : pj[2 * k];
                pj[k] = kp + __shfl_xor_sync(0xffffffffu, snd, 1);
            }
            bool b1 = lane & 2;
            {
                float snd = b1 ? pj[0] : pj[1];
                float kp  = b1 ? pj[1] : pj[0];
                pj[0] = kp + __shfl_xor_sync(0xffffffffu, snd, 2);
            }
            pj[0] += __shfl_xor_sync(0xffffffffu, pj[0], 4);
        }
        float q = pj[0];                  // edge (lane&3) logit, dup at xor4
        float qm = fmaxf(q, __shfl_xor_sync(0xffffffffu, q, 1));
        qm = fmaxf(qm, __shfl_xor_sync(0xffffffffu, qm, 2));
        float nm = fmaxf(m, qm);
        float wq = __expf(q - nm);
        float wm = __expf(m - nm);
        m = nm;
        float wv[4];
        int gbase = lane & 24;
#pragma unroll
        for (int j = 0; j < 4; j++)
            wv[j] = __shfl_sync(0xffffffffu, wq, gbase + j);
        float dsum = (wv[0] + wv[1]) + (wv[2] + wv[3]);
        d = d * wm + dsum;
        acc.x *= wm; acc.y *= wm; acc.z *= wm; acc.w *= wm;
#pragma unroll
        for (int j = 0; j < 4; j++) {
            acc.x += wv[j] * xv[j].x;
            acc.y += wv[j] * xv[j].y;
            acc.z += wv[j] * xv[j].z;
            acc.w += wv[j] * xv[j].w;
        }
    }

    // ---- remainder ----
    for (; e < end; e++) {
        int src = __ldg(&g_esrc[e]);
        float4 xv = *(const float4*)(g_xr + src * CH + c0);
        float t0 = xlv.x + xv.x;
        float t1 = xlv.y + xv.y;
        float t2 = xlv.z + xv.z;
        float t3 = xlv.w + xv.w;
        float q = a6.x * t0 + a4.x * fabsf(t0);
        q += a6.y * t1 + a4.y * fabsf(t1);
        q += a6.z * t2 + a4.z * fabsf(t2);
        q += a6.w * t3 + a4.w * fabsf(t3);
#pragma unroll
        for (int o = 1; o < 8; o <<= 1)
            q += __shfl_xor_sync(0xffffffffu, q, o);

        float nm = fmaxf(m, q);
        float wm = __expf(m - nm);
        float wq = __expf(q - nm);
        d = d * wm + wq;
        acc.x = acc.x * wm + wq * xv.x;
        acc.y = acc.y * wm + wq * xv.y;
        acc.z = acc.z * wm + wq * xv.z;
        acc.w = acc.w * wm + wq * xv.w;
        m = nm;
    }

    float inv = 1.0f / d;
    const float4 bv = *(const float4*)(bias + c0);
    float4 r = make_float4(acc.x * inv + bv.x, acc.y * inv + bv.y,
                           acc.z * inv + bv.z, acc.w * inv + bv.w);
    *(float4*)(out + i * CH + c0) = r;
}

// ---------------- launch ------------------------------------------------------
extern "C" void kernel_launch(void* const* d_in, const int* in_sizes, int n_in,
                              void* d_out, int out_size) {
    const float* x    = (const float*)d_in[0];
    const int*   ei   = (const int*)d_in[1];     // int32 (JAX x64 disabled)
    const float* Wl   = (const float*)d_in[2];
    const float* bl   = (const float*)d_in[3];
    const float* Wr   = (const float*)d_in[4];
    const float* br   = (const float*)d_in[5];
    const float* att  = (const float*)d_in[6];
    const float* bias = (const float*)d_in[7];
    float*       out  = (float*)d_out;

    csr_gemm_kernel<<<NB_SCAN + NB_MMA, 256>>>(x, ei, Wl, bl, Wr, br);
    agg_kernel<<<(N_NODES * 32 + 255) / 256, 256>>>(att, bias, out);
}